// round 8
// baseline (speedup 1.0000x reference)
#include <cuda_runtime.h>

// 10-qubit, 3-layer state-vector sim, batch 32. One CTA/sample, 512 thr, 2 amps/thr.
// Layout A: j = [w3..w0 | l4..l0 | k]   (t = w*32+lane, regs = k)
//   alpha: qubit 9 (reg bit 0) + qubits 8..4 (lane bits 0..4, shfl) -> 6 gates, no barrier
// Layout B: j = [k | l4..l0 | w3..w0]
//   beta:  qubit 0 (reg bit 9) + qubits 1..3 (lane bits 4..2, shfl) -> 4 gates
// Ring-CNOT perm (GF(2)-linear) folded into the B->A ring-gather and final scatter.
// Output: float32 real part, (32,1024) row-major.

#define NT 512
#define DIM 1024
#define NGATES 30

__device__ __forceinline__ float2 cmulc(float2 a, float2 b) {
    return make_float2(a.x * b.x - a.y * b.y, a.x * b.y + a.y * b.x);
}
__device__ __forceinline__ float2 cfma2(float2 m0, float2 a, float2 m1, float2 b) {
    float re = fmaf(m0.x, a.x, fmaf(-m0.y, a.y, fmaf(m1.x, b.x, -m1.y * b.y)));
    float im = fmaf(m0.x, a.y, fmaf(m0.y, a.x, fmaf(m1.x, b.y,  m1.y * b.x)));
    return make_float2(re, im);
}

// ring(j): bit_i' = b_i^b_{i+1} (i=0..7), b8' = b8^b9^b0, b9' = b9^b0
__device__ __forceinline__ int ring_f(int j) {
    int low = (j ^ (j >> 1)) & 0xFF;
    int b8  = ((j >> 8) ^ (j >> 9) ^ j) & 1;
    int b9  = ((j >> 9) ^ j) & 1;
    return low | (b8 << 8) | (b9 << 9);
}
// ring^{-1}: apply p01,p12,...,p89 then p90
__device__ __forceinline__ int ring_inv(int i) {
    int idx = i;
    #pragma unroll
    for (int b = 9; b >= 1; b--)
        if ((idx >> b) & 1) idx ^= (1 << (b - 1));
    if (idx & 1) idx ^= (1 << 9);
    return idx;
}

__device__ __forceinline__ int phys(int j) { return j ^ ((j >> 4) & 15); }

// butterfly across the register bit (pair a[0],a[1])
__device__ __forceinline__ void bf_reg(float2 a[2], const float2* g) {
    float2 n0 = cfma2(g[0], a[0], g[1], a[1]);
    float2 n1 = cfma2(g[2], a[0], g[3], a[1]);
    a[0] = n0; a[1] = n1;
}
// butterfly across lane bit (mask msk) via shfl.xor
__device__ __forceinline__ void bf_sh(float2 a[2], const float2* g, int lane, int msk) {
    const bool hi = (lane & msk) != 0;
    const float2 cA = hi ? g[3] : g[0];   // own-amp coeff
    const float2 cB = hi ? g[2] : g[1];   // partner coeff
    #pragma unroll
    for (int k = 0; k < 2; k++) {
        float2 o;
        o.x = __shfl_xor_sync(0xffffffffu, a[k].x, msk);
        o.y = __shfl_xor_sync(0xffffffffu, a[k].y, msk);
        a[k] = cfma2(cA, a[k], cB, o);
    }
}

// alpha: qubit 9 on reg bit, qubits 8..4 on lane bits 0..4
__device__ __forceinline__ void alpha_gates(float2 a[2], const float2 (*G)[4], int lane) {
    bf_reg(a, G[9]);
    bf_sh(a, G[8], lane, 1);
    bf_sh(a, G[7], lane, 2);
    bf_sh(a, G[6], lane, 4);
    bf_sh(a, G[5], lane, 8);
    bf_sh(a, G[4], lane, 16);
}
// beta: qubit 0 on reg bit, qubits 1..3 on lane bits 4..2
__device__ __forceinline__ void beta_gates(float2 a[2], const float2 (*G)[4], int lane) {
    bf_reg(a, G[0]);
    bf_sh(a, G[1], lane, 16);
    bf_sh(a, G[2], lane, 8);
    bf_sh(a, G[3], lane, 4);
}

__global__ __launch_bounds__(NT, 1)
void statevec_kernel(const float* __restrict__ X,      // (32,20)
                     const float* __restrict__ W,      // 90
                     const float* __restrict__ B,      // 90
                     float* __restrict__ out)          // (32,1024) f32 = Re(state)
{
    __shared__ float2 buf0[DIM];
    __shared__ float2 buf1[DIM];
    __shared__ float2 gates[NGATES][4];

    const int s    = blockIdx.x;
    const int t    = threadIdx.x;
    const int lane = t & 31;
    const int w    = t >> 5;          // 0..15

    if (t < NGATES) {
        const int a0 = t * 3;
        const float phi   = fmaf(X[s * 20 + (a0    ) % 20], W[a0    ], B[a0    ]);
        const float theta = fmaf(X[s * 20 + (a0 + 1) % 20], W[a0 + 1], B[a0 + 1]);
        const float omega = fmaf(X[s * 20 + (a0 + 2) % 20], W[a0 + 2], B[a0 + 2]);

        float stq, ctq;  __sincosf(theta * 0.5f, &stq, &ctq);
        float sp,  cp;   __sincosf((phi + omega) * 0.5f, &sp, &cp);
        float sm,  cm;   __sincosf((phi - omega) * 0.5f, &sm, &cm);

        gates[t][0] = make_float2( cp * ctq, -sp * ctq);
        gates[t][1] = make_float2(-cm * stq, -sm * stq);
        gates[t][2] = make_float2( cm * stq, -sm * stq);
        gates[t][3] = make_float2( cp * ctq,  sp * ctq);
    }
    __syncthreads();                                           // bar 1

    // Layout-A / Layout-B index bases for this thread
    const int jA0 = (w << 6) | (lane << 1);                    // k in bit 0
    const int jB0 = (lane << 4) | w;                           // k in bit 9
    const int pA0 = phys(jA0),        pA1 = phys(jA0 | 1);
    const int pB0 = phys(jB0),        pB1 = phys(jB0 | (1 << 9));
    const int rA0 = phys(ring_f(jA0));                        // ring-gather sources
    const int rA1 = phys(ring_f(jA0) ^ 0x301);                // ring(jA^1)=ring(jA)^0x301

    float2 a[2];

    // ================= layer 0 =================
    {
        const float2 (*G)[4] = (const float2 (*)[4])&gates[0];
        // alpha on |0...0>: closed form, only w==0 nonzero
        if (w == 0) {
            float2 c = make_float2(1.0f, 0.0f);
            #pragma unroll
            for (int i = 0; i < 5; i++)                        // lane bit i -> qubit 8-i
                c = cmulc(c, G[8 - i][((lane >> i) & 1) ? 2 : 0]);
            a[0] = cmulc(c, G[9][0]);
            a[1] = cmulc(c, G[9][2]);
        } else {
            a[0] = make_float2(0.0f, 0.0f);
            a[1] = make_float2(0.0f, 0.0f);
        }
        buf0[pA0] = a[0];  buf0[pA1] = a[1];
        __syncthreads();                                       // bar 2
        a[0] = buf0[pB0];  a[1] = buf0[pB1];
        beta_gates(a, G, lane);
        buf1[pB0] = a[0];  buf1[pB1] = a[1];
        __syncthreads();                                       // bar 3
    }
    // ================= layer 1 =================
    {
        const float2 (*G)[4] = (const float2 (*)[4])&gates[10];
        a[0] = buf1[rA0];  a[1] = buf1[rA1];                   // ring gather
        alpha_gates(a, G, lane);
        buf0[pA0] = a[0];  buf0[pA1] = a[1];
        __syncthreads();                                       // bar 4
        a[0] = buf0[pB0];  a[1] = buf0[pB1];
        beta_gates(a, G, lane);
        buf1[pB0] = a[0];  buf1[pB1] = a[1];
        __syncthreads();                                       // bar 5
    }
    // ================= layer 2 =================
    {
        const float2 (*G)[4] = (const float2 (*)[4])&gates[20];
        a[0] = buf1[rA0];  a[1] = buf1[rA1];                   // ring gather
        alpha_gates(a, G, lane);
        buf0[pA0] = a[0];  buf0[pA1] = a[1];
        __syncthreads();                                       // bar 6
        a[0] = buf0[pB0];  a[1] = buf0[pB1];
        beta_gates(a, G, lane);
    }

    // final: layer-2 ring perm via inverse scatter; real part only
    float* o = out + s * DIM;
    o[ring_inv(jB0)]            = a[0].x;
    o[ring_inv(jB0 | (1 << 9))] = a[1].x;
}

extern "C" void kernel_launch(void* const* d_in, const int* in_sizes, int n_in,
                              void* d_out, int out_size) {
    const float* X = (const float*)d_in[0];   // (32,20)
    const float* W = (const float*)d_in[1];   // 90
    const float* B = (const float*)d_in[2];   // 90
    statevec_kernel<<<32, NT>>>(X, W, B, (float*)d_out);
}

// round 9
// speedup vs baseline: 1.0332x; 1.0332x over previous
#include <cuda_runtime.h>

// 10-qubit, 3-layer state-vector sim, batch 32. One CTA/sample, 256 thr, 4 amps/thr.
// Packed f32x2 arithmetic: one k-bit is a SIMD spectator lane, halving FFMA count.
// Layout A: j = [w2 w1 w0 | l4..l0 | kbf ksp]  (alpha: qubits 3..7 shfl, 8 reg-bf, 9 spectator)
// Layout B: j = [l4 l3 l2 | w2 w1 w0 | l1 l0 | ksp kbf] (beta: qubits 0,1,2 shfl, 9 reg-bf, 8 spectator)
// Ring-CNOT (GF(2)-linear) folded into B->A ring-gather + final scatter.
// Output: float32 real part, (32,1024) row-major.

#define NT 256
#define DIM 1024
#define NGATES 30

typedef unsigned long long u64;

__device__ __forceinline__ u64 pack2(float lo, float hi) {
    u64 r; asm("mov.b64 %0, {%1, %2};" : "=l"(r) : "f"(lo), "f"(hi)); return r;
}
__device__ __forceinline__ void unpack2(float& lo, float& hi, u64 v) {
    asm("mov.b64 {%0, %1}, %2;" : "=f"(lo), "=f"(hi) : "l"(v));
}
__device__ __forceinline__ u64 fma2(u64 a, u64 b, u64 c) {
    u64 d; asm("fma.rn.f32x2 %0, %1, %2, %3;" : "=l"(d) : "l"(a), "l"(b), "l"(c)); return d;
}
__device__ __forceinline__ u64 mul2(u64 a, u64 b) {
    u64 d; asm("mul.rn.f32x2 %0, %1, %2;" : "=l"(d) : "l"(a), "l"(b)); return d;
}

struct cv { u64 x; u64 y; };   // packed complex pair: two amplitudes' (re), (im)

// n = cA*a + cB*b, coefficients given as splat triples {(x,x), (-y,-y), (y,y)}
__device__ __forceinline__ cv cmadd2(const u64* cA, const u64* cB, cv a, cv b) {
    cv n;
    n.x = fma2(cA[0], a.x, fma2(cA[1], a.y, fma2(cB[0], b.x, mul2(cB[1], b.y))));
    n.y = fma2(cA[0], a.y, fma2(cA[2], a.x, fma2(cB[0], b.y, mul2(cB[2], b.x))));
    return n;
}

__device__ __forceinline__ float2 cmulc(float2 a, float2 b) {
    return make_float2(a.x * b.x - a.y * b.y, a.x * b.y + a.y * b.x);
}

// ring(j): bit_i' = b_i^b_{i+1} (i=0..7), b8' = b8^b9^b0, b9' = b9^b0
__device__ __forceinline__ int ring_f(int j) {
    int low = (j ^ (j >> 1)) & 0xFF;
    int b8  = ((j >> 8) ^ (j >> 9) ^ j) & 1;
    int b9  = ((j >> 9) ^ j) & 1;
    return low | (b8 << 8) | (b9 << 9);
}
__device__ __forceinline__ int ring_inv(int i) {
    int idx = i;
    #pragma unroll
    for (int b = 9; b >= 1; b--)
        if ((idx >> b) & 1) idx ^= (1 << (b - 1));
    if (idx & 1) idx ^= (1 << 9);
    return idx;
}

__device__ __forceinline__ int phys(int j) { return j ^ ((j >> 6) & 15); }

__device__ __forceinline__ u64 shfl2(u64 v, int msk) {
    float lo, hi; unpack2(lo, hi, v);
    lo = __shfl_xor_sync(0xffffffffu, lo, msk);
    hi = __shfl_xor_sync(0xffffffffu, hi, msk);
    return pack2(lo, hi);
}

// butterfly across lane bit msk on both vector groups
__device__ __forceinline__ void bf_sh(cv v[2], const u64 (*gs)[3], int lane, int msk) {
    const bool hi = (lane & msk) != 0;
    const u64* cA = gs[hi ? 3 : 0];
    const u64* cB = gs[hi ? 2 : 1];
    #pragma unroll
    for (int g = 0; g < 2; g++) {
        cv o; o.x = shfl2(v[g].x, msk); o.y = shfl2(v[g].y, msk);
        v[g] = cmadd2(cA, cB, v[g], o);
    }
}
// butterfly across the vector-group axis (reg bit)
__device__ __forceinline__ void bf_reg(cv v[2], const u64 (*gs)[3]) {
    cv n0 = cmadd2(gs[0], gs[1], v[0], v[1]);
    cv n1 = cmadd2(gs[2], gs[3], v[0], v[1]);
    v[0] = n0; v[1] = n1;
}

__global__ __launch_bounds__(NT, 2)
void statevec_kernel(const float* __restrict__ X,      // (32,20)
                     const float* __restrict__ W,      // 90
                     const float* __restrict__ B,      // 90
                     float* __restrict__ out)          // (32,1024) f32 = Re(state)
{
    __shared__ float2 buf0[DIM];
    __shared__ float2 buf1[DIM];
    __shared__ u64    gs[NGATES][4][3];   // splats: (x,x), (-y,-y), (y,y) per entry
    __shared__ float2 gsc[NGATES][4];     // scalar entries (layer-0 closed form)

    const int s    = blockIdx.x;
    const int t    = threadIdx.x;
    const int lane = t & 31;
    const int w    = t >> 5;          // 0..7

    if (t < NGATES) {
        const int a0 = t * 3;
        const float phi   = fmaf(X[s * 20 + (a0    ) % 20], W[a0    ], B[a0    ]);
        const float theta = fmaf(X[s * 20 + (a0 + 1) % 20], W[a0 + 1], B[a0 + 1]);
        const float omega = fmaf(X[s * 20 + (a0 + 2) % 20], W[a0 + 2], B[a0 + 2]);

        float stq, ctq;  __sincosf(theta * 0.5f, &stq, &ctq);
        float sp,  cp;   __sincosf((phi + omega) * 0.5f, &sp, &cp);
        float sm,  cm;   __sincosf((phi - omega) * 0.5f, &sm, &cm);

        float2 m[4];
        m[0] = make_float2( cp * ctq, -sp * ctq);
        m[1] = make_float2(-cm * stq, -sm * stq);
        m[2] = make_float2( cm * stq, -sm * stq);
        m[3] = make_float2( cp * ctq,  sp * ctq);
        #pragma unroll
        for (int e = 0; e < 4; e++) {
            gsc[t][e]  = m[e];
            gs[t][e][0] = pack2( m[e].x,  m[e].x);
            gs[t][e][1] = pack2(-m[e].y, -m[e].y);
            gs[t][e][2] = pack2( m[e].y,  m[e].y);
        }
    }
    __syncthreads();                                           // bar 1

    // index bases
    const int jA0 = (w << 7) | (lane << 2);                    // k = (bf<<1)|sp at bits 1..0
    const int jB0 = ((lane >> 2) << 7) | (w << 4) | ((lane & 3) << 2);  // k=(sp<<1)|bf at bits 1..0
    const int rb  = ring_f(jA0);                               // ring-gather base

    cv v[2];   // v[bf]: slots = spectator bit (alpha: qubit 9; beta: qubit 8)

    #pragma unroll
    for (int l = 0; l < 3; l++) {
        const int g0 = l * 10;

        // ---------------- alpha: qubits 3..7 (shfl), 8 (reg), 9 spectator ----------------
        if (l == 0) {
            // closed form on |0...0>: nonzero only for w==0 (qubits 0,1,2 = 0), sp=0
            if (w == 0) {
                float2 c = make_float2(1.0f, 0.0f);
                #pragma unroll
                for (int i = 0; i < 5; i++)                    // lane bit i -> qubit 7-i
                    c = cmulc(c, gsc[7 - i][((lane >> i) & 1) ? 2 : 0]);
                float2 a0 = cmulc(c, gsc[8][0]);               // bf=0 (qubit-8 bit 0)
                float2 a1 = cmulc(c, gsc[8][2]);               // bf=1
                v[0].x = pack2(a0.x, 0.0f); v[0].y = pack2(a0.y, 0.0f);
                v[1].x = pack2(a1.x, 0.0f); v[1].y = pack2(a1.y, 0.0f);
            } else {
                v[0].x = v[0].y = v[1].x = v[1].y = 0ull;
            }
        } else {
            // ring gather from buf1 (layout A logical indices through RING)
            float2 a00 = buf1[phys(rb)];            // k=0: bf0 sp0
            float2 a01 = buf1[phys(rb ^ 0x301)];    // k=1: bf0 sp1   (ring_f(1)=0x301)
            float2 a10 = buf1[phys(rb ^ 0x003)];    // k=2: bf1 sp0   (ring_f(2)=3)
            float2 a11 = buf1[phys(rb ^ 0x302)];    // k=3: bf1 sp1
            v[0].x = pack2(a00.x, a01.x); v[0].y = pack2(a00.y, a01.y);
            v[1].x = pack2(a10.x, a11.x); v[1].y = pack2(a10.y, a11.y);

            bf_reg(v, gs[g0 + 8]);                             // qubit 8
            bf_sh(v, gs[g0 + 7], lane, 1);                     // qubit 7
            bf_sh(v, gs[g0 + 6], lane, 2);
            bf_sh(v, gs[g0 + 5], lane, 4);
            bf_sh(v, gs[g0 + 4], lane, 8);
            bf_sh(v, gs[g0 + 3], lane, 16);                    // qubit 3
        }

        // ---- exchange A -> B (store scalar amps at layout-A logical indices) ----
        {
            float x0, x1, y0, y1;
            unpack2(x0, x1, v[0].x); unpack2(y0, y1, v[0].y);
            buf0[phys(jA0 | 0)] = make_float2(x0, y0);         // bf0 sp0
            buf0[phys(jA0 | 1)] = make_float2(x1, y1);         // bf0 sp1
            unpack2(x0, x1, v[1].x); unpack2(y0, y1, v[1].y);
            buf0[phys(jA0 | 2)] = make_float2(x0, y0);         // bf1 sp0
            buf0[phys(jA0 | 3)] = make_float2(x1, y1);         // bf1 sp1
        }
        __syncthreads();                                       // bars 2,4,6
        {
            // layout B: k = (sp<<1)|bf ; sp = qubit-8 bit (j bit1), bf = qubit-9 bit (j bit0)
            float2 b00 = buf0[phys(jB0 | 0)];   // bf0 sp0
            float2 b01 = buf0[phys(jB0 | 2)];   // bf0 sp1
            float2 b10 = buf0[phys(jB0 | 1)];   // bf1 sp0
            float2 b11 = buf0[phys(jB0 | 3)];   // bf1 sp1
            v[0].x = pack2(b00.x, b01.x); v[0].y = pack2(b00.y, b01.y);
            v[1].x = pack2(b10.x, b11.x); v[1].y = pack2(b10.y, b11.y);
        }

        // ---------------- beta: qubits 0,1,2 (shfl), 9 (reg), 8 spectator ----------------
        bf_reg(v, gs[g0 + 9]);                                 // qubit 9
        bf_sh(v, gs[g0 + 0], lane, 16);                        // qubit 0 (j bit9 = l4)
        bf_sh(v, gs[g0 + 1], lane, 8);                         // qubit 1
        bf_sh(v, gs[g0 + 2], lane, 4);                         // qubit 2

        if (l < 2) {
            float x0, x1, y0, y1;
            unpack2(x0, x1, v[0].x); unpack2(y0, y1, v[0].y);
            buf1[phys(jB0 | 0)] = make_float2(x0, y0);         // bf0 sp0
            buf1[phys(jB0 | 2)] = make_float2(x1, y1);         // bf0 sp1
            unpack2(x0, x1, v[1].x); unpack2(y0, y1, v[1].y);
            buf1[phys(jB0 | 1)] = make_float2(x0, y0);         // bf1 sp0
            buf1[phys(jB0 | 3)] = make_float2(x1, y1);         // bf1 sp1
            __syncthreads();                                   // bars 3,5
        }
    }

    // ---- final: layer-2 ring perm via inverse scatter; real part only ----
    float* o = out + s * DIM;
    float x0, x1, dummy0, dummy1;
    unpack2(x0, x1, v[0].x);
    o[ring_inv(jB0 | 0)] = x0;
    o[ring_inv(jB0 | 2)] = x1;
    unpack2(x0, x1, v[1].x);
    o[ring_inv(jB0 | 1)] = x0;
    o[ring_inv(jB0 | 3)] = x1;
    (void)dummy0; (void)dummy1;
}

extern "C" void kernel_launch(void* const* d_in, const int* in_sizes, int n_in,
                              void* d_out, int out_size) {
    const float* X = (const float*)d_in[0];   // (32,20)
    const float* W = (const float*)d_in[1];   // 90
    const float* B = (const float*)d_in[2];   // 90
    statevec_kernel<<<32, NT>>>(X, W, B, (float*)d_out);
}